// round 12
// baseline (speedup 1.0000x reference)
#include <cuda_runtime.h>
#include <cuda_fp16.h>
#include <cstdint>

// Problem constants
#define B_   256
#define NV_  196
#define LT_  32
#define CI_  768
#define CT_  512
#define NROWS (B_*NV_)      // 50176
#define KVROWS (B_*LT_)     // 8192
#define KVW   1536          // fused K|V output width

// -------------------- scratch (device globals; no allocation) --------------------
__device__ __half g_vis_h [(size_t)NROWS * CI_];
__device__ __half g_text_h[(size_t)KVROWS * CT_];
__device__ __half g_wqT  [(size_t)CI_ * CI_];
__device__ __half g_wkvT [(size_t)KVW * CT_];
__device__ __half g_w1T  [(size_t)CI_ * CI_];
__device__ __half g_fused_h[(size_t)NROWS * CI_];
__device__ __half g_qh [(size_t)NROWS * CI_];
__device__ __half g_kvh[(size_t)KVROWS * KVW];
__device__ float g_bkv[KVW];
__device__ float g_part[(size_t)6 * NROWS * 2];

// -------------------- small helpers --------------------
__device__ __forceinline__ float qgelu(float x) {
    return x / (1.0f + __expf(-1.702f * x));
}
__device__ __forceinline__ uint32_t pack_h2(__half a, __half b) {
    uint32_t la = (uint32_t)__half_as_ushort(a);
    uint32_t lb = (uint32_t)__half_as_ushort(b);
    return la | (lb << 16);
}
__device__ __forceinline__ uint32_t smem_u32(const void* p) {
    uint32_t a;
    asm("{ .reg .u64 t; cvta.to.shared.u64 t, %1; cvt.u32.u64 %0, t; }" : "=r"(a) : "l"(p));
    return a;
}
// packed f32x2 helpers (FFMA2)
__device__ __forceinline__ unsigned long long mk2(uint32_t lo, uint32_t hi) {
    unsigned long long r;
    asm("mov.b64 %0, {%1, %2};" : "=l"(r) : "r"(lo), "r"(hi));
    return r;
}
__device__ __forceinline__ unsigned long long pk2f(float lo, float hi) {
    unsigned long long r;
    asm("mov.b64 %0, {%1, %2};" : "=l"(r) : "f"(lo), "f"(hi));
    return r;
}
__device__ __forceinline__ unsigned long long pkdup(float x) {
    unsigned long long r;
    asm("mov.b64 %0, {%1, %1};" : "=l"(r) : "f"(x));
    return r;
}
__device__ __forceinline__ unsigned long long ffma2(unsigned long long a,
                                                    unsigned long long b,
                                                    unsigned long long c) {
    unsigned long long d;
    asm("fma.rn.f32x2 %0, %1, %2, %3;" : "=l"(d) : "l"(a), "l"(b), "l"(c));
    return d;
}
__device__ __forceinline__ void upk2(unsigned long long v, float& lo, float& hi) {
    asm("mov.b64 {%0, %1}, %2;" : "=f"(lo), "=f"(hi) : "l"(v));
}

// -------------------- mma / ldmatrix / cp.async primitives (base sm_103) --------
__device__ __forceinline__ void ldsm_x4(uint32_t* r, uint32_t addr) {
    asm volatile("ldmatrix.sync.aligned.m8n8.x4.shared.b16 {%0,%1,%2,%3}, [%4];"
                 : "=r"(r[0]), "=r"(r[1]), "=r"(r[2]), "=r"(r[3]) : "r"(addr));
}
__device__ __forceinline__ void mma_fp16(float* d, const uint32_t* a, const uint32_t* b) {
    asm volatile(
        "mma.sync.aligned.m16n8k16.row.col.f32.f16.f16.f32 "
        "{%0,%1,%2,%3}, {%4,%5,%6,%7}, {%8,%9}, {%0,%1,%2,%3};"
        : "+f"(d[0]), "+f"(d[1]), "+f"(d[2]), "+f"(d[3])
        : "r"(a[0]), "r"(a[1]), "r"(a[2]), "r"(a[3]), "r"(b[0]), "r"(b[1]));
}
__device__ __forceinline__ void cp_async16(uint32_t dst, const void* src) {
    asm volatile("cp.async.cg.shared.global [%0], [%1], 16;" :: "r"(dst), "l"(src));
}
__device__ __forceinline__ void cp_commit() {
    asm volatile("cp.async.commit_group;");
}
__device__ __forceinline__ void cp_wait2() {
    asm volatile("cp.async.wait_group 2;");
}

// -------------------- fp16 tensor-core GEMM (unchanged from R11) ----------------
#define SST 40
#define TILE_B (128 * SST * 2)
#define STAGE_B (2 * TILE_B)
#define NSTAGE 4
#define GEMM_SMEM (NSTAGE * STAGE_B)    // 81920 B -> 2 CTAs/SM

__device__ __forceinline__ void issue_tile(uint32_t dst, const __half* src,
                                           int ld, int tid) {
#pragma unroll
    for (int it = 0; it < 2; it++) {
        int id = tid + it * 256;
        int r = id >> 2, c = id & 3;
        cp_async16(dst + r * (SST * 2) + c * 16, src + (size_t)r * ld + c * 8);
    }
}

template<int KDIM, int OUTN, int DO_HEAD, int OUT_HALF>
__global__ __launch_bounds__(256, 2)
void gemm_mma(const __half* __restrict__ A_g, const __half* __restrict__ B_g,
              const float* __restrict__ bias, void* __restrict__ Cv,
              const float* __restrict__ W2p, float* __restrict__ part) {
    extern __shared__ char smem[];
    const int tid = threadIdx.x;
    const int lane = tid & 31;
    const int wid = tid >> 5;
    const int wm = wid & 3;
    const int wn = wid >> 2;
    const int n0 = blockIdx.x * 128;
    const int m0 = blockIdx.y * 128;

    const uint32_t sbase = smem_u32(smem);

    const __half* Ah = A_g + (size_t)m0 * KDIM;
    const __half* Bh = B_g + (size_t)n0 * KDIM;

    constexpr int NC = KDIM / 32;

    float acc[2][8][4];
#pragma unroll
    for (int i = 0; i < 2; i++)
#pragma unroll
        for (int j = 0; j < 8; j++)
#pragma unroll
            for (int k = 0; k < 4; k++) acc[i][j][k] = 0.f;

#pragma unroll
    for (int p = 0; p < 3; p++) {
        uint32_t st = sbase + p * STAGE_B;
        issue_tile(st,          Ah + p * 32, KDIM, tid);
        issue_tile(st + TILE_B, Bh + p * 32, KDIM, tid);
        cp_commit();
    }

    const int a_row = wm * 32 + (lane & 15);
    const int a_colb = ((lane >> 4) << 3) * 2;
    const int b_row = wn * 64 + (lane & 7) + ((lane >> 4) << 3);
    const int b_colb = (((lane >> 3) & 1) << 3) * 2;

    for (int c = 0; c < NC; c++) {
        cp_wait2();
        __syncthreads();
        if (c + 3 < NC) {
            uint32_t st = sbase + ((c + 3) % NSTAGE) * STAGE_B;
            int k0 = (c + 3) * 32;
            issue_tile(st,          Ah + k0, KDIM, tid);
            issue_tile(st + TILE_B, Bh + k0, KDIM, tid);
        }
        cp_commit();

        uint32_t st = sbase + (c % NSTAGE) * STAGE_B;
#pragma unroll
        for (int ks = 0; ks < 2; ks++) {
            const int kb = ks * 32;
            uint32_t Af[2][4];
#pragma unroll
            for (int mi = 0; mi < 2; mi++) {
                uint32_t arow = (a_row + mi * 16) * (SST * 2) + kb + a_colb;
                ldsm_x4(Af[mi], st + arow);
            }
            uint32_t Bf[4][4];
#pragma unroll
            for (int ni2 = 0; ni2 < 4; ni2++) {
                uint32_t brow = (b_row + ni2 * 16) * (SST * 2) + kb + b_colb;
                ldsm_x4(Bf[ni2], st + TILE_B + brow);
            }
#pragma unroll
            for (int mi = 0; mi < 2; mi++)
#pragma unroll
                for (int ni = 0; ni < 8; ni++) {
                    const int ni2 = ni >> 1, od = (ni & 1) * 2;
                    mma_fp16(acc[mi][ni], Af[mi], &Bf[ni2][od]);
                }
        }
    }

    if (!DO_HEAD) {
#pragma unroll
        for (int mi = 0; mi < 2; mi++) {
            int row0 = m0 + wm * 32 + mi * 16 + (lane >> 2);
#pragma unroll
            for (int ni = 0; ni < 8; ni++) {
                int col = n0 + wn * 64 + ni * 8 + (lane & 3) * 2;
                float b0 = bias[col], b1 = bias[col + 1];
                float v0 = acc[mi][ni][0] + b0;
                float v1 = acc[mi][ni][1] + b1;
                float v2 = acc[mi][ni][2] + b0;
                float v3 = acc[mi][ni][3] + b1;
                if (OUT_HALF) {
                    __half* Ch = (__half*)Cv;
                    *(uint32_t*)(Ch + (size_t)row0 * OUTN + col) =
                        pack_h2(__float2half(v0), __float2half(v1));
                    *(uint32_t*)(Ch + (size_t)(row0 + 8) * OUTN + col) =
                        pack_h2(__float2half(v2), __float2half(v3));
                } else {
                    float* C = (float*)Cv;
                    *(float2*)(C + (size_t)row0 * OUTN + col)       = make_float2(v0, v1);
                    *(float2*)(C + (size_t)(row0 + 8) * OUTN + col) = make_float2(v2, v3);
                }
            }
        }
    } else {
        __syncthreads();
        float* red = (float*)smem;
        const float2* w2 = (const float2*)W2p;
#pragma unroll
        for (int mi = 0; mi < 2; mi++) {
            float pa0 = 0.f, pa1 = 0.f, pb0 = 0.f, pb1 = 0.f;
#pragma unroll
            for (int ni = 0; ni < 8; ni++) {
                int col = n0 + wn * 64 + ni * 8 + (lane & 3) * 2;
                float b0 = bias[col], b1 = bias[col + 1];
                float v0 = qgelu(acc[mi][ni][0] + b0);
                float v1 = qgelu(acc[mi][ni][1] + b1);
                float v2 = qgelu(acc[mi][ni][2] + b0);
                float v3 = qgelu(acc[mi][ni][3] + b1);
                float2 wA = w2[col], wB = w2[col + 1];
                pa0 += v0 * wA.x + v1 * wB.x;
                pa1 += v0 * wA.y + v1 * wB.y;
                pb0 += v2 * wA.x + v3 * wB.x;
                pb1 += v2 * wA.y + v3 * wB.y;
            }
#pragma unroll
            for (int off = 1; off <= 2; off <<= 1) {
                pa0 += __shfl_xor_sync(0xffffffffu, pa0, off);
                pa1 += __shfl_xor_sync(0xffffffffu, pa1, off);
                pb0 += __shfl_xor_sync(0xffffffffu, pb0, off);
                pb1 += __shfl_xor_sync(0xffffffffu, pb1, off);
            }
            if ((lane & 3) == 0 && wn == 0) {
                int lrA = wm * 32 + mi * 16 + (lane >> 2);
                red[lrA * 2]           = pa0;
                red[lrA * 2 + 1]       = pa1;
                red[(lrA + 8) * 2]     = pb0;
                red[(lrA + 8) * 2 + 1] = pb1;
            }
        }
        __syncthreads();
#pragma unroll
        for (int mi = 0; mi < 2; mi++) {
            if (wn == 1) {
                float pa0 = 0.f, pa1 = 0.f, pb0 = 0.f, pb1 = 0.f;
#pragma unroll
                for (int ni = 0; ni < 8; ni++) {
                    int col = n0 + wn * 64 + ni * 8 + (lane & 3) * 2;
                    float b0 = bias[col], b1 = bias[col + 1];
                    float v0 = qgelu(acc[mi][ni][0] + b0);
                    float v1 = qgelu(acc[mi][ni][1] + b1);
                    float v2 = qgelu(acc[mi][ni][2] + b0);
                    float v3 = qgelu(acc[mi][ni][3] + b1);
                    float2 wA = w2[col], wB = w2[col + 1];
                    pa0 += v0 * wA.x + v1 * wB.x;
                    pa1 += v0 * wA.y + v1 * wB.y;
                    pb0 += v2 * wA.x + v3 * wB.x;
                    pb1 += v2 * wA.y + v3 * wB.y;
                }
#pragma unroll
                for (int off = 1; off <= 2; off <<= 1) {
                    pa0 += __shfl_xor_sync(0xffffffffu, pa0, off);
                    pa1 += __shfl_xor_sync(0xffffffffu, pa1, off);
                    pb0 += __shfl_xor_sync(0xffffffffu, pb0, off);
                    pb1 += __shfl_xor_sync(0xffffffffu, pb1, off);
                }
                if ((lane & 3) == 0) {
                    int lrA = wm * 32 + mi * 16 + (lane >> 2);
                    red[lrA * 2]           += pa0;
                    red[lrA * 2 + 1]       += pa1;
                    red[(lrA + 8) * 2]     += pb0;
                    red[(lrA + 8) * 2 + 1] += pb1;
                }
            }
        }
        __syncthreads();
        int row = tid >> 1, comp = tid & 1;
        part[((size_t)blockIdx.x * NROWS + m0 + row) * 2 + comp] = red[row * 2 + comp];
    }
}

// -------------------- fp32 -> fp16 convert --------------------
__global__ __launch_bounds__(256)
void cvt_kernel(const float* __restrict__ x, __half* __restrict__ h, int n4) {
    int i = blockIdx.x * blockDim.x + threadIdx.x;
    if (i >= n4) return;
    float4 v = ((const float4*)x)[i];
    ((uint2*)h)[i] = make_uint2(pack_h2(__float2half(v.x), __float2half(v.y)),
                                pack_h2(__float2half(v.z), __float2half(v.w)));
}

// -------------------- weight transpose -> fp16: W[K,N] -> T[N,K] ----------
__global__ __launch_bounds__(256)
void transpose_cvt(const float* __restrict__ W, __half* __restrict__ T, int K, int N) {
    __shared__ float t[32][33];
    int n0 = blockIdx.x * 32, k0 = blockIdx.y * 32;
    int tx = threadIdx.x & 31, ty = threadIdx.x >> 5;
#pragma unroll
    for (int s = 0; s < 4; s++)
        t[ty + 8 * s][tx] = W[(size_t)(k0 + ty + 8 * s) * N + n0 + tx];
    __syncthreads();
#pragma unroll
    for (int s = 0; s < 4; s++) {
        int n = n0 + ty + 8 * s;
        int k = k0 + tx;
        T[(size_t)n * K + k] = __float2half(t[tx][ty + 8 * s]);
    }
}

// -------------------- bias concat for fused KV --------------------
__global__ void concat_bias(const float* __restrict__ bk, const float* __restrict__ bv,
                            float* __restrict__ bkv) {
    int i = blockIdx.x * blockDim.x + threadIdx.x;
    if (i < 768) bkv[i] = bk[i];
    else if (i < 1536) bkv[i] = bv[i - 768];
}

// -------------------- attention (FFMA2 inner loops) --------------------
// K/V converted to fp32 pairs in smem at CTA load; q and ctx packed f32x2.
__global__ __launch_bounds__(256)
void attn_kernel(const __half* __restrict__ q_s, const __half* __restrict__ kv,
                 const float* __restrict__ vis, __half* __restrict__ f_h) {
    int h = blockIdx.x;
    int b = blockIdx.y;
    __shared__ uint4 ksm[32][16];   // [l][u]: floats d=4u..4u+3 (as bits)
    __shared__ uint4 vsm[32][16];
    int tid = threadIdx.x;

    const __half* kbase = kv + (size_t)b * 32 * KVW + h * 64;
    const __half* vbase = kbase + 768;
#pragma unroll
    for (int it = 0; it < 2; it++) {
        int i = tid + it * 256;
        int l = i >> 4, u = i & 15;
        uint2 kh = *(const uint2*)(kbase + (size_t)l * KVW + u * 4);
        float2 ka = __half22float2(*(__half2*)&kh.x);
        float2 kb2 = __half22float2(*(__half2*)&kh.y);
        ksm[l][u] = make_uint4(__float_as_uint(ka.x), __float_as_uint(ka.y),
                               __float_as_uint(kb2.x), __float_as_uint(kb2.y));
        uint2 vh2 = *(const uint2*)(vbase + (size_t)l * KVW + u * 4);
        float2 va = __half22float2(*(__half2*)&vh2.x);
        float2 vb = __half22float2(*(__half2*)&vh2.y);
        vsm[l][u] = make_uint4(__float_as_uint(va.x), __float_as_uint(va.y),
                               __float_as_uint(vb.x), __float_as_uint(vb.y));
    }
    __syncthreads();

    int n = tid;
    if (n >= 196) return;
    size_t rowoff = (size_t)(b * 196 + n) * 768 + h * 64;

    // q as 32 packed f32x2 pairs
    unsigned long long qp[32];
    {
        const uint2* qrow = (const uint2*)(q_s + rowoff);
#pragma unroll
        for (int d = 0; d < 16; d++) {
            uint2 u = qrow[d];
            float2 f0 = __half22float2(*(__half2*)&u.x);
            float2 f1 = __half22float2(*(__half2*)&u.y);
            qp[2 * d]     = pk2f(f0.x, f0.y);
            qp[2 * d + 1] = pk2f(f1.x, f1.y);
        }
    }

    float s[32];
#pragma unroll
    for (int l = 0; l < 32; l++) {
        unsigned long long a0 = 0ull, a1 = 0ull;
#pragma unroll
        for (int u = 0; u < 16; u++) {
            uint4 kk = ksm[l][u];
            a0 = ffma2(qp[2 * u],     mk2(kk.x, kk.y), a0);
            a1 = ffma2(qp[2 * u + 1], mk2(kk.z, kk.w), a1);
        }
        float l0, h0, l1, h1;
        upk2(a0, l0, h0);
        upk2(a1, l1, h1);
        s[l] = (l0 + h0 + l1 + h1) * 0.125f;
    }
    float m = s[0];
#pragma unroll
    for (int l = 1; l < 32; l++) m = fmaxf(m, s[l]);
    float sum = 0.f;
#pragma unroll
    for (int l = 0; l < 32; l++) { s[l] = __expf(s[l] - m); sum += s[l]; }
    float inv = 1.0f / sum;
#pragma unroll
    for (int l = 0; l < 32; l++) s[l] *= inv;

    // ctx as 32 packed pairs
    unsigned long long ctx[32];
#pragma unroll
    for (int p = 0; p < 32; p++) ctx[p] = 0ull;
#pragma unroll
    for (int l = 0; l < 32; l++) {
        unsigned long long pd = pkdup(s[l]);
#pragma unroll
        for (int u = 0; u < 16; u++) {
            uint4 vv = vsm[l][u];
            ctx[2 * u]     = ffma2(pd, mk2(vv.x, vv.y), ctx[2 * u]);
            ctx[2 * u + 1] = ffma2(pd, mk2(vv.z, vv.w), ctx[2 * u + 1]);
        }
    }

    const float4* visrow = (const float4*)(vis + rowoff);
    uint2* hrow = (uint2*)(f_h + rowoff);
#pragma unroll
    for (int u = 0; u < 16; u++) {
        float c0, c1, c2, c3;
        upk2(ctx[2 * u], c0, c1);
        upk2(ctx[2 * u + 1], c2, c3);
        float4 r = visrow[u];
        hrow[u] = make_uint2(
            pack_h2(__float2half(c0 + r.x), __float2half(c1 + r.y)),
            pack_h2(__float2half(c2 + r.z), __float2half(c3 + r.w)));
    }
}

// -------------------- head reduce: sum 6 partials + bias; fill rel -------------
__global__ __launch_bounds__(256)
void reduce_head(const float* __restrict__ part, const float* __restrict__ b2,
                 float* __restrict__ out) {
    int i = blockIdx.x * blockDim.x + threadIdx.x;
    if (i >= NROWS) return;
    float a0 = b2[0], a1 = b2[1];
#pragma unroll
    for (int p = 0; p < 6; p++) {
        a0 += part[((size_t)p * NROWS + i) * 2];
        a1 += part[((size_t)p * NROWS + i) * 2 + 1];
    }
    out[(size_t)i * 2]     = a0;
    out[(size_t)i * 2 + 1] = a1;
    out[(size_t)NROWS * 2 + i] = 1.0f / 32.0f;   // rel_BN == 1/Lt exactly
}

// -------------------- host launch --------------------
extern "C" void kernel_launch(void* const* d_in, const int* in_sizes, int n_in,
                              void* d_out, int out_size) {
    const float* vis  = (const float*)d_in[0];
    const float* text = (const float*)d_in[1];
    const float* Wq   = (const float*)d_in[2];
    const float* bq   = (const float*)d_in[3];
    const float* Wk   = (const float*)d_in[4];
    const float* bk   = (const float*)d_in[5];
    const float* Wv   = (const float*)d_in[6];
    const float* bv   = (const float*)d_in[7];
    const float* W1   = (const float*)d_in[8];
    const float* b1   = (const float*)d_in[9];
    const float* W2   = (const float*)d_in[10];
    const float* b2   = (const float*)d_in[11];
    float* out = (float*)d_out;

    __half *vh, *th, *wq, *wkv, *w1, *fh, *qh, *kvh;
    float *bkv, *partp;
    cudaGetSymbolAddress((void**)&vh,   g_vis_h);
    cudaGetSymbolAddress((void**)&th,   g_text_h);
    cudaGetSymbolAddress((void**)&wq,   g_wqT);
    cudaGetSymbolAddress((void**)&wkv,  g_wkvT);
    cudaGetSymbolAddress((void**)&w1,   g_w1T);
    cudaGetSymbolAddress((void**)&fh,   g_fused_h);
    cudaGetSymbolAddress((void**)&qh,   g_qh);
    cudaGetSymbolAddress((void**)&kvh,  g_kvh);
    cudaGetSymbolAddress((void**)&bkv,  g_bkv);
    cudaGetSymbolAddress((void**)&partp, g_part);

    cudaFuncSetAttribute(gemm_mma<768, 768, 0, 1>, cudaFuncAttributeMaxDynamicSharedMemorySize, GEMM_SMEM);
    cudaFuncSetAttribute(gemm_mma<512, KVW, 0, 1>, cudaFuncAttributeMaxDynamicSharedMemorySize, GEMM_SMEM);
    cudaFuncSetAttribute(gemm_mma<768, 768, 1, 0>, cudaFuncAttributeMaxDynamicSharedMemorySize, GEMM_SMEM);

    // 1: convert vis -> fp16
    {
        int n4 = NROWS * CI_ / 4;
        cvt_kernel<<<(n4 + 255) / 256, 256>>>(vis, vh, n4);
    }
    // 2: convert text -> fp16
    {
        int n4 = KVROWS * CT_ / 4;
        cvt_kernel<<<(n4 + 255) / 256, 256>>>(text, th, n4);
    }
    // 3: transpose Wq
    transpose_cvt<<<dim3(CI_ / 32, CI_ / 32), 256>>>(Wq, wq, CI_, CI_);
    // 4: Q projection (fp16 out)  <-- profiler slot
    gemm_mma<768, 768, 0, 1><<<dim3(6, NROWS / 128), 256, GEMM_SMEM>>>(
        vh, wq, bq, qh, nullptr, nullptr);
    // 5-6: transpose Wk, Wv into fused wkv
    transpose_cvt<<<dim3(CI_ / 32, CT_ / 32), 256>>>(Wk, wkv, CT_, CI_);
    transpose_cvt<<<dim3(CI_ / 32, CT_ / 32), 256>>>(Wv, wkv + (size_t)768 * CT_, CT_, CI_);
    // 7: bias concat
    concat_bias<<<6, 256>>>(bk, bv, bkv);
    // 8: fused K|V projection (fp16 out)
    gemm_mma<512, KVW, 0, 1><<<dim3(12, KVROWS / 128), 256, GEMM_SMEM>>>(
        th, wkv, bkv, kvh, nullptr, nullptr);
    // 9: attention + residual -> fused fp16
    attn_kernel<<<dim3(12, B_), 256>>>(qh, kvh, vis, fh);
    // 10: transpose W1
    transpose_cvt<<<dim3(CI_ / 32, CI_ / 32), 256>>>(W1, w1, CI_, CI_);
    // 11: MLP1 + gelu + fused W2 head -> partials
    gemm_mma<768, 768, 1, 0><<<dim3(6, NROWS / 128), 256, GEMM_SMEM>>>(
        fh, w1, b1, nullptr, W2, partp);
    // 12: reduce partials + bias; fill rel
    reduce_head<<<(NROWS + 255) / 256, 256>>>(partp, b2, out);
}

// round 14
// speedup vs baseline: 1.6040x; 1.6040x over previous
#include <cuda_runtime.h>
#include <cuda_fp16.h>
#include <cstdint>

// Problem constants
#define B_   256
#define NV_  196
#define LT_  32
#define CI_  768
#define CT_  512
#define NROWS (B_*NV_)      // 50176
#define KVROWS (B_*LT_)     // 8192
#define KVW   1536          // fused K|V output width

// -------------------- scratch (device globals; no allocation) --------------------
__device__ __half g_vis_h [(size_t)NROWS * CI_];
__device__ __half g_text_h[(size_t)KVROWS * CT_];
__device__ __half g_wqT  [(size_t)CI_ * CI_];
__device__ __half g_wkvT [(size_t)KVW * CT_];
__device__ __half g_w1T  [(size_t)CI_ * CI_];
__device__ __half g_fused_h[(size_t)NROWS * CI_];
__device__ __half g_qh [(size_t)NROWS * CI_];
__device__ __half g_kvh[(size_t)KVROWS * KVW];
__device__ float g_bkv[KVW];
__device__ float g_part[(size_t)6 * NROWS * 2];

// -------------------- small helpers --------------------
__device__ __forceinline__ float qgelu(float x) {
    return x / (1.0f + __expf(-1.702f * x));
}
__device__ __forceinline__ uint32_t pack_h2(__half a, __half b) {
    uint32_t la = (uint32_t)__half_as_ushort(a);
    uint32_t lb = (uint32_t)__half_as_ushort(b);
    return la | (lb << 16);
}
__device__ __forceinline__ uint32_t smem_u32(const void* p) {
    uint32_t a;
    asm("{ .reg .u64 t; cvta.to.shared.u64 t, %1; cvt.u32.u64 %0, t; }" : "=r"(a) : "l"(p));
    return a;
}

// -------------------- mma / ldmatrix / cp.async primitives (base sm_103) --------
__device__ __forceinline__ void ldsm_x4(uint32_t* r, uint32_t addr) {
    asm volatile("ldmatrix.sync.aligned.m8n8.x4.shared.b16 {%0,%1,%2,%3}, [%4];"
                 : "=r"(r[0]), "=r"(r[1]), "=r"(r[2]), "=r"(r[3]) : "r"(addr));
}
__device__ __forceinline__ void mma_fp16(float* d, const uint32_t* a, const uint32_t* b) {
    asm volatile(
        "mma.sync.aligned.m16n8k16.row.col.f32.f16.f16.f32 "
        "{%0,%1,%2,%3}, {%4,%5,%6,%7}, {%8,%9}, {%0,%1,%2,%3};"
        : "+f"(d[0]), "+f"(d[1]), "+f"(d[2]), "+f"(d[3])
        : "r"(a[0]), "r"(a[1]), "r"(a[2]), "r"(a[3]), "r"(b[0]), "r"(b[1]));
}
__device__ __forceinline__ void cp_async16(uint32_t dst, const void* src) {
    asm volatile("cp.async.cg.shared.global [%0], [%1], 16;" :: "r"(dst), "l"(src));
}
__device__ __forceinline__ void cp_commit() {
    asm volatile("cp.async.commit_group;");
}
__device__ __forceinline__ void cp_wait2() {
    asm volatile("cp.async.wait_group 2;");
}

// -------------------- fp16 tensor-core GEMM (unchanged from R11) ----------------
#define SST 40
#define TILE_B (128 * SST * 2)
#define STAGE_B (2 * TILE_B)
#define NSTAGE 4
#define GEMM_SMEM (NSTAGE * STAGE_B)    // 81920 B -> 2 CTAs/SM

__device__ __forceinline__ void issue_tile(uint32_t dst, const __half* src,
                                           int ld, int tid) {
#pragma unroll
    for (int it = 0; it < 2; it++) {
        int id = tid + it * 256;
        int r = id >> 2, c = id & 3;
        cp_async16(dst + r * (SST * 2) + c * 16, src + (size_t)r * ld + c * 8);
    }
}

template<int KDIM, int OUTN, int DO_HEAD, int OUT_HALF>
__global__ __launch_bounds__(256, 2)
void gemm_mma(const __half* __restrict__ A_g, const __half* __restrict__ B_g,
              const float* __restrict__ bias, void* __restrict__ Cv,
              const float* __restrict__ W2p, float* __restrict__ part) {
    extern __shared__ char smem[];
    const int tid = threadIdx.x;
    const int lane = tid & 31;
    const int wid = tid >> 5;
    const int wm = wid & 3;
    const int wn = wid >> 2;
    const int n0 = blockIdx.x * 128;
    const int m0 = blockIdx.y * 128;

    const uint32_t sbase = smem_u32(smem);

    const __half* Ah = A_g + (size_t)m0 * KDIM;
    const __half* Bh = B_g + (size_t)n0 * KDIM;

    constexpr int NC = KDIM / 32;

    float acc[2][8][4];
#pragma unroll
    for (int i = 0; i < 2; i++)
#pragma unroll
        for (int j = 0; j < 8; j++)
#pragma unroll
            for (int k = 0; k < 4; k++) acc[i][j][k] = 0.f;

#pragma unroll
    for (int p = 0; p < 3; p++) {
        uint32_t st = sbase + p * STAGE_B;
        issue_tile(st,          Ah + p * 32, KDIM, tid);
        issue_tile(st + TILE_B, Bh + p * 32, KDIM, tid);
        cp_commit();
    }

    const int a_row = wm * 32 + (lane & 15);
    const int a_colb = ((lane >> 4) << 3) * 2;
    const int b_row = wn * 64 + (lane & 7) + ((lane >> 4) << 3);
    const int b_colb = (((lane >> 3) & 1) << 3) * 2;

    for (int c = 0; c < NC; c++) {
        cp_wait2();
        __syncthreads();
        if (c + 3 < NC) {
            uint32_t st = sbase + ((c + 3) % NSTAGE) * STAGE_B;
            int k0 = (c + 3) * 32;
            issue_tile(st,          Ah + k0, KDIM, tid);
            issue_tile(st + TILE_B, Bh + k0, KDIM, tid);
        }
        cp_commit();

        uint32_t st = sbase + (c % NSTAGE) * STAGE_B;
#pragma unroll
        for (int ks = 0; ks < 2; ks++) {
            const int kb = ks * 32;
            uint32_t Af[2][4];
#pragma unroll
            for (int mi = 0; mi < 2; mi++) {
                uint32_t arow = (a_row + mi * 16) * (SST * 2) + kb + a_colb;
                ldsm_x4(Af[mi], st + arow);
            }
            uint32_t Bf[4][4];
#pragma unroll
            for (int ni2 = 0; ni2 < 4; ni2++) {
                uint32_t brow = (b_row + ni2 * 16) * (SST * 2) + kb + b_colb;
                ldsm_x4(Bf[ni2], st + TILE_B + brow);
            }
#pragma unroll
            for (int mi = 0; mi < 2; mi++)
#pragma unroll
                for (int ni = 0; ni < 8; ni++) {
                    const int ni2 = ni >> 1, od = (ni & 1) * 2;
                    mma_fp16(acc[mi][ni], Af[mi], &Bf[ni2][od]);
                }
        }
    }

    if (!DO_HEAD) {
#pragma unroll
        for (int mi = 0; mi < 2; mi++) {
            int row0 = m0 + wm * 32 + mi * 16 + (lane >> 2);
#pragma unroll
            for (int ni = 0; ni < 8; ni++) {
                int col = n0 + wn * 64 + ni * 8 + (lane & 3) * 2;
                float b0 = bias[col], b1 = bias[col + 1];
                float v0 = acc[mi][ni][0] + b0;
                float v1 = acc[mi][ni][1] + b1;
                float v2 = acc[mi][ni][2] + b0;
                float v3 = acc[mi][ni][3] + b1;
                if (OUT_HALF) {
                    __half* Ch = (__half*)Cv;
                    *(uint32_t*)(Ch + (size_t)row0 * OUTN + col) =
                        pack_h2(__float2half(v0), __float2half(v1));
                    *(uint32_t*)(Ch + (size_t)(row0 + 8) * OUTN + col) =
                        pack_h2(__float2half(v2), __float2half(v3));
                } else {
                    float* C = (float*)Cv;
                    *(float2*)(C + (size_t)row0 * OUTN + col)       = make_float2(v0, v1);
                    *(float2*)(C + (size_t)(row0 + 8) * OUTN + col) = make_float2(v2, v3);
                }
            }
        }
    } else {
        __syncthreads();
        float* red = (float*)smem;
        const float2* w2 = (const float2*)W2p;
#pragma unroll
        for (int mi = 0; mi < 2; mi++) {
            float pa0 = 0.f, pa1 = 0.f, pb0 = 0.f, pb1 = 0.f;
#pragma unroll
            for (int ni = 0; ni < 8; ni++) {
                int col = n0 + wn * 64 + ni * 8 + (lane & 3) * 2;
                float b0 = bias[col], b1 = bias[col + 1];
                float v0 = qgelu(acc[mi][ni][0] + b0);
                float v1 = qgelu(acc[mi][ni][1] + b1);
                float v2 = qgelu(acc[mi][ni][2] + b0);
                float v3 = qgelu(acc[mi][ni][3] + b1);
                float2 wA = w2[col], wB = w2[col + 1];
                pa0 += v0 * wA.x + v1 * wB.x;
                pa1 += v0 * wA.y + v1 * wB.y;
                pb0 += v2 * wA.x + v3 * wB.x;
                pb1 += v2 * wA.y + v3 * wB.y;
            }
#pragma unroll
            for (int off = 1; off <= 2; off <<= 1) {
                pa0 += __shfl_xor_sync(0xffffffffu, pa0, off);
                pa1 += __shfl_xor_sync(0xffffffffu, pa1, off);
                pb0 += __shfl_xor_sync(0xffffffffu, pb0, off);
                pb1 += __shfl_xor_sync(0xffffffffu, pb1, off);
            }
            if ((lane & 3) == 0 && wn == 0) {
                int lrA = wm * 32 + mi * 16 + (lane >> 2);
                red[lrA * 2]           = pa0;
                red[lrA * 2 + 1]       = pa1;
                red[(lrA + 8) * 2]     = pb0;
                red[(lrA + 8) * 2 + 1] = pb1;
            }
        }
        __syncthreads();
#pragma unroll
        for (int mi = 0; mi < 2; mi++) {
            if (wn == 1) {
                float pa0 = 0.f, pa1 = 0.f, pb0 = 0.f, pb1 = 0.f;
#pragma unroll
                for (int ni = 0; ni < 8; ni++) {
                    int col = n0 + wn * 64 + ni * 8 + (lane & 3) * 2;
                    float b0 = bias[col], b1 = bias[col + 1];
                    float v0 = qgelu(acc[mi][ni][0] + b0);
                    float v1 = qgelu(acc[mi][ni][1] + b1);
                    float v2 = qgelu(acc[mi][ni][2] + b0);
                    float v3 = qgelu(acc[mi][ni][3] + b1);
                    float2 wA = w2[col], wB = w2[col + 1];
                    pa0 += v0 * wA.x + v1 * wB.x;
                    pa1 += v0 * wA.y + v1 * wB.y;
                    pb0 += v2 * wA.x + v3 * wB.x;
                    pb1 += v2 * wA.y + v3 * wB.y;
                }
#pragma unroll
                for (int off = 1; off <= 2; off <<= 1) {
                    pa0 += __shfl_xor_sync(0xffffffffu, pa0, off);
                    pa1 += __shfl_xor_sync(0xffffffffu, pa1, off);
                    pb0 += __shfl_xor_sync(0xffffffffu, pb0, off);
                    pb1 += __shfl_xor_sync(0xffffffffu, pb1, off);
                }
                if ((lane & 3) == 0) {
                    int lrA = wm * 32 + mi * 16 + (lane >> 2);
                    red[lrA * 2]           += pa0;
                    red[lrA * 2 + 1]       += pa1;
                    red[(lrA + 8) * 2]     += pb0;
                    red[(lrA + 8) * 2 + 1] += pb1;
                }
            }
        }
        __syncthreads();
        int row = tid >> 1, comp = tid & 1;
        part[((size_t)blockIdx.x * NROWS + m0 + row) * 2 + comp] = red[row * 2 + comp];
    }
}

// -------------------- fp32 -> fp16 convert --------------------
__global__ __launch_bounds__(256)
void cvt_kernel(const float* __restrict__ x, __half* __restrict__ h, int n4) {
    int i = blockIdx.x * blockDim.x + threadIdx.x;
    if (i >= n4) return;
    float4 v = ((const float4*)x)[i];
    ((uint2*)h)[i] = make_uint2(pack_h2(__float2half(v.x), __float2half(v.y)),
                                pack_h2(__float2half(v.z), __float2half(v.w)));
}

// -------------------- weight transpose -> fp16: W[K,N] -> T[N,K] ----------
__global__ __launch_bounds__(256)
void transpose_cvt(const float* __restrict__ W, __half* __restrict__ T, int K, int N) {
    __shared__ float t[32][33];
    int n0 = blockIdx.x * 32, k0 = blockIdx.y * 32;
    int tx = threadIdx.x & 31, ty = threadIdx.x >> 5;
#pragma unroll
    for (int s = 0; s < 4; s++)
        t[ty + 8 * s][tx] = W[(size_t)(k0 + ty + 8 * s) * N + n0 + tx];
    __syncthreads();
#pragma unroll
    for (int s = 0; s < 4; s++) {
        int n = n0 + ty + 8 * s;
        int k = k0 + tx;
        T[(size_t)n * K + k] = __float2half(t[tx][ty + 8 * s]);
    }
}

// -------------------- bias concat for fused KV --------------------
__global__ void concat_bias(const float* __restrict__ bk, const float* __restrict__ bv,
                            float* __restrict__ bkv) {
    int i = blockIdx.x * blockDim.x + threadIdx.x;
    if (i < 768) bkv[i] = bk[i];
    else if (i < 1536) bkv[i] = bv[i - 768];
}

// -------------------- attention (R11 form); 224 threads; fp16 residual --------
__global__ __launch_bounds__(224)
void attn_kernel(const __half* __restrict__ q_s, const __half* __restrict__ kv,
                 const __half* __restrict__ vis_h, __half* __restrict__ f_h) {
    int h = blockIdx.x;
    int b = blockIdx.y;
    __shared__ uint4 ksm[32][8];   // 32 rows x 64 halves
    __shared__ uint4 vsm[32][8];
    int tid = threadIdx.x;

    const __half* kbase = kv + (size_t)b * 32 * KVW + h * 64;
    const __half* vbase = kbase + 768;
    for (int i = tid; i < 256; i += 224) {
        int l = i >> 3, u = i & 7;
        ksm[l][u] = *(const uint4*)(kbase + (size_t)l * KVW + u * 8);
        vsm[l][u] = *(const uint4*)(vbase + (size_t)l * KVW + u * 8);
    }
    __syncthreads();

    int n = tid;
    if (n >= 196) return;
    size_t rowoff = (size_t)(b * 196 + n) * 768 + h * 64;
    const uint2* qrow = (const uint2*)(q_s + rowoff);   // 16 x (4 halves)
    float4 q4[16];
#pragma unroll
    for (int d = 0; d < 16; d++) {
        uint2 u = qrow[d];
        float2 f0 = __half22float2(*(__half2*)&u.x);
        float2 f1 = __half22float2(*(__half2*)&u.y);
        q4[d] = make_float4(f0.x, f0.y, f1.x, f1.y);
    }

    float s[32];
#pragma unroll
    for (int l = 0; l < 32; l++) {
        float acc = 0.f;
#pragma unroll
        for (int u = 0; u < 8; u++) {
            uint4 kk = ksm[l][u];
            float2 k0 = __half22float2(*(__half2*)&kk.x);
            float2 k1 = __half22float2(*(__half2*)&kk.y);
            float2 k2 = __half22float2(*(__half2*)&kk.z);
            float2 k3 = __half22float2(*(__half2*)&kk.w);
            float4 qa = q4[u * 2], qb = q4[u * 2 + 1];
            acc += qa.x * k0.x + qa.y * k0.y + qa.z * k1.x + qa.w * k1.y
                 + qb.x * k2.x + qb.y * k2.y + qb.z * k3.x + qb.w * k3.y;
        }
        s[l] = acc * 0.125f;
    }
    float m = s[0];
#pragma unroll
    for (int l = 1; l < 32; l++) m = fmaxf(m, s[l]);
    float sum = 0.f;
#pragma unroll
    for (int l = 0; l < 32; l++) { s[l] = __expf(s[l] - m); sum += s[l]; }
    float inv = 1.0f / sum;
#pragma unroll
    for (int l = 0; l < 32; l++) s[l] *= inv;

    const uint4* visrow = (const uint4*)(vis_h + rowoff);  // 8 halves per uint4
    uint2* hrow = (uint2*)(f_h + rowoff);
    for (int u = 0; u < 8; u++) {
        float a0 = 0.f, a1 = 0.f, a2 = 0.f, a3 = 0.f, a4 = 0.f, a5 = 0.f, a6 = 0.f, a7 = 0.f;
#pragma unroll
        for (int l = 0; l < 32; l++) {
            uint4 vv = vsm[l][u];
            float2 v0 = __half22float2(*(__half2*)&vv.x);
            float2 v1 = __half22float2(*(__half2*)&vv.y);
            float2 v2 = __half22float2(*(__half2*)&vv.z);
            float2 v3 = __half22float2(*(__half2*)&vv.w);
            float p = s[l];
            a0 += p * v0.x; a1 += p * v0.y; a2 += p * v1.x; a3 += p * v1.y;
            a4 += p * v2.x; a5 += p * v2.y; a6 += p * v3.x; a7 += p * v3.y;
        }
        uint4 rv = visrow[u];
        float2 r0 = __half22float2(*(__half2*)&rv.x);
        float2 r1 = __half22float2(*(__half2*)&rv.y);
        float2 r2 = __half22float2(*(__half2*)&rv.z);
        float2 r3 = __half22float2(*(__half2*)&rv.w);
        hrow[u * 2] = make_uint2(
            pack_h2(__float2half(a0 + r0.x), __float2half(a1 + r0.y)),
            pack_h2(__float2half(a2 + r1.x), __float2half(a3 + r1.y)));
        hrow[u * 2 + 1] = make_uint2(
            pack_h2(__float2half(a4 + r2.x), __float2half(a5 + r2.y)),
            pack_h2(__float2half(a6 + r3.x), __float2half(a7 + r3.y)));
    }
}

// -------------------- head reduce: sum 6 partials + bias; fill rel -------------
__global__ __launch_bounds__(256)
void reduce_head(const float* __restrict__ part, const float* __restrict__ b2,
                 float* __restrict__ out) {
    int i = blockIdx.x * blockDim.x + threadIdx.x;
    if (i >= NROWS) return;
    float a0 = b2[0], a1 = b2[1];
#pragma unroll
    for (int p = 0; p < 6; p++) {
        a0 += part[((size_t)p * NROWS + i) * 2];
        a1 += part[((size_t)p * NROWS + i) * 2 + 1];
    }
    out[(size_t)i * 2]     = a0;
    out[(size_t)i * 2 + 1] = a1;
    out[(size_t)NROWS * 2 + i] = 1.0f / 32.0f;   // rel_BN == 1/Lt exactly
}

// -------------------- host launch --------------------
extern "C" void kernel_launch(void* const* d_in, const int* in_sizes, int n_in,
                              void* d_out, int out_size) {
    const float* vis  = (const float*)d_in[0];
    const float* text = (const float*)d_in[1];
    const float* Wq   = (const float*)d_in[2];
    const float* bq   = (const float*)d_in[3];
    const float* Wk   = (const float*)d_in[4];
    const float* bk   = (const float*)d_in[5];
    const float* Wv   = (const float*)d_in[6];
    const float* bv   = (const float*)d_in[7];
    const float* W1   = (const float*)d_in[8];
    const float* b1   = (const float*)d_in[9];
    const float* W2   = (const float*)d_in[10];
    const float* b2   = (const float*)d_in[11];
    float* out = (float*)d_out;

    __half *vh, *th, *wq, *wkv, *w1, *fh, *qh, *kvh;
    float *bkv, *partp;
    cudaGetSymbolAddress((void**)&vh,   g_vis_h);
    cudaGetSymbolAddress((void**)&th,   g_text_h);
    cudaGetSymbolAddress((void**)&wq,   g_wqT);
    cudaGetSymbolAddress((void**)&wkv,  g_wkvT);
    cudaGetSymbolAddress((void**)&w1,   g_w1T);
    cudaGetSymbolAddress((void**)&fh,   g_fused_h);
    cudaGetSymbolAddress((void**)&qh,   g_qh);
    cudaGetSymbolAddress((void**)&kvh,  g_kvh);
    cudaGetSymbolAddress((void**)&bkv,  g_bkv);
    cudaGetSymbolAddress((void**)&partp, g_part);

    cudaFuncSetAttribute(gemm_mma<768, 768, 0, 1>, cudaFuncAttributeMaxDynamicSharedMemorySize, GEMM_SMEM);
    cudaFuncSetAttribute(gemm_mma<512, KVW, 0, 1>, cudaFuncAttributeMaxDynamicSharedMemorySize, GEMM_SMEM);
    cudaFuncSetAttribute(gemm_mma<768, 768, 1, 0>, cudaFuncAttributeMaxDynamicSharedMemorySize, GEMM_SMEM);

    // 1: convert vis -> fp16
    {
        int n4 = NROWS * CI_ / 4;
        cvt_kernel<<<(n4 + 255) / 256, 256>>>(vis, vh, n4);
    }
    // 2: convert text -> fp16
    {
        int n4 = KVROWS * CT_ / 4;
        cvt_kernel<<<(n4 + 255) / 256, 256>>>(text, th, n4);
    }
    // 3: transpose Wq
    transpose_cvt<<<dim3(CI_ / 32, CI_ / 32), 256>>>(Wq, wq, CI_, CI_);
    // 4: Q projection (fp16 out)  <-- profiler slot
    gemm_mma<768, 768, 0, 1><<<dim3(6, NROWS / 128), 256, GEMM_SMEM>>>(
        vh, wq, bq, qh, nullptr, nullptr);
    // 5-6: transpose Wk, Wv into fused wkv
    transpose_cvt<<<dim3(CI_ / 32, CT_ / 32), 256>>>(Wk, wkv, CT_, CI_);
    transpose_cvt<<<dim3(CI_ / 32, CT_ / 32), 256>>>(Wv, wkv + (size_t)768 * CT_, CT_, CI_);
    // 7: bias concat
    concat_bias<<<6, 256>>>(bk, bv, bkv);
    // 8: fused K|V projection (fp16 out)
    gemm_mma<512, KVW, 0, 1><<<dim3(12, KVROWS / 128), 256, GEMM_SMEM>>>(
        th, wkv, bkv, kvh, nullptr, nullptr);
    // 9: attention + residual (fp16 vis) -> fused fp16
    attn_kernel<<<dim3(12, B_), 224>>>(qh, kvh, vh, fh);
    // 10: transpose W1
    transpose_cvt<<<dim3(CI_ / 32, CI_ / 32), 256>>>(W1, w1, CI_, CI_);
    // 11: MLP1 + gelu + fused W2 head -> partials
    gemm_mma<768, 768, 1, 0><<<dim3(6, NROWS / 128), 256, GEMM_SMEM>>>(
        fh, w1, b1, nullptr, W2, partp);
    // 12: reduce partials + bias; fill rel
    reduce_head<<<(NROWS + 255) / 256, 256>>>(partp, b2, out);
}

// round 16
// speedup vs baseline: 2.2965x; 1.4318x over previous
#include <cuda_runtime.h>
#include <cuda_fp16.h>
#include <cstdint>

// Problem constants
#define B_   256
#define NV_  196
#define LT_  32
#define CI_  768
#define CT_  512
#define NROWS (B_*NV_)      // 50176
#define KVROWS (B_*LT_)     // 8192
#define KVW   1536          // fused K|V output width

// -------------------- scratch (device globals; no allocation) --------------------
__device__ __half g_vis_h [(size_t)NROWS * CI_];
__device__ __half g_text_h[(size_t)KVROWS * CT_];
__device__ __half g_wqT  [(size_t)CI_ * CI_];
__device__ __half g_wkvT [(size_t)KVW * CT_];
__device__ __half g_w1T  [(size_t)CI_ * CI_];
__device__ __half g_fused_h[(size_t)NROWS * CI_];
__device__ __half g_qh [(size_t)(NROWS + 16) * CI_];   // +16 rows padding for attn tiles
__device__ __half g_kvh[(size_t)KVROWS * KVW];
__device__ float g_bkv[KVW];
__device__ float g_part[(size_t)6 * NROWS * 2];

// -------------------- small helpers --------------------
__device__ __forceinline__ float qgelu(float x) {
    return x / (1.0f + __expf(-1.702f * x));
}
__device__ __forceinline__ uint32_t pack_h2(__half a, __half b) {
    uint32_t la = (uint32_t)__half_as_ushort(a);
    uint32_t lb = (uint32_t)__half_as_ushort(b);
    return la | (lb << 16);
}
__device__ __forceinline__ uint32_t pack_h2f(float a, float b) {
    return pack_h2(__float2half(a), __float2half(b));
}
__device__ __forceinline__ uint32_t smem_u32(const void* p) {
    uint32_t a;
    asm("{ .reg .u64 t; cvta.to.shared.u64 t, %1; cvt.u32.u64 %0, t; }" : "=r"(a) : "l"(p));
    return a;
}
// fast exp: degree-5 poly for 2^f + exponent bit-add (FMA pipe, avoids MUFU)
__device__ __forceinline__ float fexp(float x) {
    x = fmaxf(x, -60.0f);
    float t = x * 1.4426950408889634f;
    float r = rintf(t);
    float f = t - r;
    float p = 0.0013333558f;
    p = fmaf(p, f, 0.0096181291f);
    p = fmaf(p, f, 0.0555041087f);
    p = fmaf(p, f, 0.2402265070f);
    p = fmaf(p, f, 0.6931471806f);
    p = fmaf(p, f, 1.0f);
    int i = (int)r;
    return __int_as_float(__float_as_int(p) + (i << 23));
}

// -------------------- mma / ldmatrix / cp.async primitives (base sm_103) --------
__device__ __forceinline__ void ldsm_x4(uint32_t* r, uint32_t addr) {
    asm volatile("ldmatrix.sync.aligned.m8n8.x4.shared.b16 {%0,%1,%2,%3}, [%4];"
                 : "=r"(r[0]), "=r"(r[1]), "=r"(r[2]), "=r"(r[3]) : "r"(addr));
}
__device__ __forceinline__ void mma_fp16(float* d, const uint32_t* a, const uint32_t* b) {
    asm volatile(
        "mma.sync.aligned.m16n8k16.row.col.f32.f16.f16.f32 "
        "{%0,%1,%2,%3}, {%4,%5,%6,%7}, {%8,%9}, {%0,%1,%2,%3};"
        : "+f"(d[0]), "+f"(d[1]), "+f"(d[2]), "+f"(d[3])
        : "r"(a[0]), "r"(a[1]), "r"(a[2]), "r"(a[3]), "r"(b[0]), "r"(b[1]));
}
__device__ __forceinline__ void cp_async16(uint32_t dst, const void* src) {
    asm volatile("cp.async.cg.shared.global [%0], [%1], 16;" :: "r"(dst), "l"(src));
}
__device__ __forceinline__ void cp_commit() {
    asm volatile("cp.async.commit_group;");
}
__device__ __forceinline__ void cp_wait2() {
    asm volatile("cp.async.wait_group 2;");
}

// -------------------- fp16 tensor-core GEMM (unchanged from R14) ----------------
#define SST 40
#define TILE_B (128 * SST * 2)
#define STAGE_B (2 * TILE_B)
#define NSTAGE 4
#define GEMM_SMEM (NSTAGE * STAGE_B)    // 81920 B -> 2 CTAs/SM

__device__ __forceinline__ void issue_tile(uint32_t dst, const __half* src,
                                           int ld, int tid) {
#pragma unroll
    for (int it = 0; it < 2; it++) {
        int id = tid + it * 256;
        int r = id >> 2, c = id & 3;
        cp_async16(dst + r * (SST * 2) + c * 16, src + (size_t)r * ld + c * 8);
    }
}

template<int KDIM, int OUTN, int DO_HEAD, int OUT_HALF>
__global__ __launch_bounds__(256, 2)
void gemm_mma(const __half* __restrict__ A_g, const __half* __restrict__ B_g,
              const float* __restrict__ bias, void* __restrict__ Cv,
              const float* __restrict__ W2p, float* __restrict__ part) {
    extern __shared__ char smem[];
    const int tid = threadIdx.x;
    const int lane = tid & 31;
    const int wid = tid >> 5;
    const int wm = wid & 3;
    const int wn = wid >> 2;
    const int n0 = blockIdx.x * 128;
    const int m0 = blockIdx.y * 128;

    const uint32_t sbase = smem_u32(smem);

    const __half* Ah = A_g + (size_t)m0 * KDIM;
    const __half* Bh = B_g + (size_t)n0 * KDIM;

    constexpr int NC = KDIM / 32;

    float acc[2][8][4];
#pragma unroll
    for (int i = 0; i < 2; i++)
#pragma unroll
        for (int j = 0; j < 8; j++)
#pragma unroll
            for (int k = 0; k < 4; k++) acc[i][j][k] = 0.f;

#pragma unroll
    for (int p = 0; p < 3; p++) {
        uint32_t st = sbase + p * STAGE_B;
        issue_tile(st,          Ah + p * 32, KDIM, tid);
        issue_tile(st + TILE_B, Bh + p * 32, KDIM, tid);
        cp_commit();
    }

    const int a_row = wm * 32 + (lane & 15);
    const int a_colb = ((lane >> 4) << 3) * 2;
    const int b_row = wn * 64 + (lane & 7) + ((lane >> 4) << 3);
    const int b_colb = (((lane >> 3) & 1) << 3) * 2;

    for (int c = 0; c < NC; c++) {
        cp_wait2();
        __syncthreads();
        if (c + 3 < NC) {
            uint32_t st = sbase + ((c + 3) % NSTAGE) * STAGE_B;
            int k0 = (c + 3) * 32;
            issue_tile(st,          Ah + k0, KDIM, tid);
            issue_tile(st + TILE_B, Bh + k0, KDIM, tid);
        }
        cp_commit();

        uint32_t st = sbase + (c % NSTAGE) * STAGE_B;
#pragma unroll
        for (int ks = 0; ks < 2; ks++) {
            const int kb = ks * 32;
            uint32_t Af[2][4];
#pragma unroll
            for (int mi = 0; mi < 2; mi++) {
                uint32_t arow = (a_row + mi * 16) * (SST * 2) + kb + a_colb;
                ldsm_x4(Af[mi], st + arow);
            }
            uint32_t Bf[4][4];
#pragma unroll
            for (int ni2 = 0; ni2 < 4; ni2++) {
                uint32_t brow = (b_row + ni2 * 16) * (SST * 2) + kb + b_colb;
                ldsm_x4(Bf[ni2], st + TILE_B + brow);
            }
#pragma unroll
            for (int mi = 0; mi < 2; mi++)
#pragma unroll
                for (int ni = 0; ni < 8; ni++) {
                    const int ni2 = ni >> 1, od = (ni & 1) * 2;
                    mma_fp16(acc[mi][ni], Af[mi], &Bf[ni2][od]);
                }
        }
    }

    if (!DO_HEAD) {
#pragma unroll
        for (int mi = 0; mi < 2; mi++) {
            int row0 = m0 + wm * 32 + mi * 16 + (lane >> 2);
#pragma unroll
            for (int ni = 0; ni < 8; ni++) {
                int col = n0 + wn * 64 + ni * 8 + (lane & 3) * 2;
                float b0 = bias[col], b1 = bias[col + 1];
                float v0 = acc[mi][ni][0] + b0;
                float v1 = acc[mi][ni][1] + b1;
                float v2 = acc[mi][ni][2] + b0;
                float v3 = acc[mi][ni][3] + b1;
                if (OUT_HALF) {
                    __half* Ch = (__half*)Cv;
                    *(uint32_t*)(Ch + (size_t)row0 * OUTN + col) =
                        pack_h2(__float2half(v0), __float2half(v1));
                    *(uint32_t*)(Ch + (size_t)(row0 + 8) * OUTN + col) =
                        pack_h2(__float2half(v2), __float2half(v3));
                } else {
                    float* C = (float*)Cv;
                    *(float2*)(C + (size_t)row0 * OUTN + col)       = make_float2(v0, v1);
                    *(float2*)(C + (size_t)(row0 + 8) * OUTN + col) = make_float2(v2, v3);
                }
            }
        }
    } else {
        __syncthreads();
        float* red = (float*)smem;
        const float2* w2 = (const float2*)W2p;
#pragma unroll
        for (int mi = 0; mi < 2; mi++) {
            float pa0 = 0.f, pa1 = 0.f, pb0 = 0.f, pb1 = 0.f;
#pragma unroll
            for (int ni = 0; ni < 8; ni++) {
                int col = n0 + wn * 64 + ni * 8 + (lane & 3) * 2;
                float b0 = bias[col], b1 = bias[col + 1];
                float v0 = qgelu(acc[mi][ni][0] + b0);
                float v1 = qgelu(acc[mi][ni][1] + b1);
                float v2 = qgelu(acc[mi][ni][2] + b0);
                float v3 = qgelu(acc[mi][ni][3] + b1);
                float2 wA = w2[col], wB = w2[col + 1];
                pa0 += v0 * wA.x + v1 * wB.x;
                pa1 += v0 * wA.y + v1 * wB.y;
                pb0 += v2 * wA.x + v3 * wB.x;
                pb1 += v2 * wA.y + v3 * wB.y;
            }
#pragma unroll
            for (int off = 1; off <= 2; off <<= 1) {
                pa0 += __shfl_xor_sync(0xffffffffu, pa0, off);
                pa1 += __shfl_xor_sync(0xffffffffu, pa1, off);
                pb0 += __shfl_xor_sync(0xffffffffu, pb0, off);
                pb1 += __shfl_xor_sync(0xffffffffu, pb1, off);
            }
            if ((lane & 3) == 0 && wn == 0) {
                int lrA = wm * 32 + mi * 16 + (lane >> 2);
                red[lrA * 2]           = pa0;
                red[lrA * 2 + 1]       = pa1;
                red[(lrA + 8) * 2]     = pb0;
                red[(lrA + 8) * 2 + 1] = pb1;
            }
        }
        __syncthreads();
#pragma unroll
        for (int mi = 0; mi < 2; mi++) {
            if (wn == 1) {
                float pa0 = 0.f, pa1 = 0.f, pb0 = 0.f, pb1 = 0.f;
#pragma unroll
                for (int ni = 0; ni < 8; ni++) {
                    int col = n0 + wn * 64 + ni * 8 + (lane & 3) * 2;
                    float b0 = bias[col], b1 = bias[col + 1];
                    float v0 = qgelu(acc[mi][ni][0] + b0);
                    float v1 = qgelu(acc[mi][ni][1] + b1);
                    float v2 = qgelu(acc[mi][ni][2] + b0);
                    float v3 = qgelu(acc[mi][ni][3] + b1);
                    float2 wA = w2[col], wB = w2[col + 1];
                    pa0 += v0 * wA.x + v1 * wB.x;
                    pa1 += v0 * wA.y + v1 * wB.y;
                    pb0 += v2 * wA.x + v3 * wB.x;
                    pb1 += v2 * wA.y + v3 * wB.y;
                }
#pragma unroll
                for (int off = 1; off <= 2; off <<= 1) {
                    pa0 += __shfl_xor_sync(0xffffffffu, pa0, off);
                    pa1 += __shfl_xor_sync(0xffffffffu, pa1, off);
                    pb0 += __shfl_xor_sync(0xffffffffu, pb0, off);
                    pb1 += __shfl_xor_sync(0xffffffffu, pb1, off);
                }
                if ((lane & 3) == 0) {
                    int lrA = wm * 32 + mi * 16 + (lane >> 2);
                    red[lrA * 2]           += pa0;
                    red[lrA * 2 + 1]       += pa1;
                    red[(lrA + 8) * 2]     += pb0;
                    red[(lrA + 8) * 2 + 1] += pb1;
                }
            }
        }
        __syncthreads();
        int row = tid >> 1, comp = tid & 1;
        part[((size_t)blockIdx.x * NROWS + m0 + row) * 2 + comp] = red[row * 2 + comp];
    }
}

// -------------------- fp32 -> fp16 convert --------------------
__global__ __launch_bounds__(256)
void cvt_kernel(const float* __restrict__ x, __half* __restrict__ h, int n4) {
    int i = blockIdx.x * blockDim.x + threadIdx.x;
    if (i >= n4) return;
    float4 v = ((const float4*)x)[i];
    ((uint2*)h)[i] = make_uint2(pack_h2(__float2half(v.x), __float2half(v.y)),
                                pack_h2(__float2half(v.z), __float2half(v.w)));
}

// -------------------- weight transpose -> fp16: W[K,N] -> T[N,K] ----------
__global__ __launch_bounds__(256)
void transpose_cvt(const float* __restrict__ W, __half* __restrict__ T, int K, int N) {
    __shared__ float t[32][33];
    int n0 = blockIdx.x * 32, k0 = blockIdx.y * 32;
    int tx = threadIdx.x & 31, ty = threadIdx.x >> 5;
#pragma unroll
    for (int s = 0; s < 4; s++)
        t[ty + 8 * s][tx] = W[(size_t)(k0 + ty + 8 * s) * N + n0 + tx];
    __syncthreads();
#pragma unroll
    for (int s = 0; s < 4; s++) {
        int n = n0 + ty + 8 * s;
        int k = k0 + tx;
        T[(size_t)n * K + k] = __float2half(t[tx][ty + 8 * s]);
    }
}

// -------------------- bias concat for fused KV --------------------
__global__ void concat_bias(const float* __restrict__ bk, const float* __restrict__ bv,
                            float* __restrict__ bkv) {
    int i = blockIdx.x * blockDim.x + threadIdx.x;
    if (i < 768) bkv[i] = bk[i];
    else if (i < 1536) bkv[i] = bv[i - 768];
}

// -------------------- MMA attention --------------------
// Block = (h, b). 128 threads / 4 warps. Q tile [208x64] (rows padded; padded
// rows computed but never stored), K [32x64], V^T [64x32] in smem.
// QK^T and PV via m16n8k16 fp16 MMAs; softmax on C-frags with poly exp.
#define QST 72    // Q/K smem row stride in halves (144 B)
#define VST 40    // V^T smem row stride in halves (80 B)

__global__ __launch_bounds__(128)
void attn_mma(const __half* __restrict__ q_s, const __half* __restrict__ kv,
              const __half* __restrict__ vis_h, __half* __restrict__ f_h) {
    __shared__ __align__(16) __half Qs[208 * QST];
    __shared__ __align__(16) __half Ks[32 * QST];
    __shared__ __align__(16) __half Vt[64 * VST];

    const int h = blockIdx.x;
    const int b = blockIdx.y;
    const int tid = threadIdx.x;
    const int lane = tid & 31;
    const int w = tid >> 5;

    // ---- stage Q tile: 208 rows x 64 halves (head h) ----
    const __half* qg = q_s + (size_t)(b * 196) * CI_ + h * 64;
#pragma unroll
    for (int it = 0; it < 13; it++) {
        int i = tid + it * 128;          // 0..1663
        int r = i >> 3, u = i & 7;
        uint4 v = *(const uint4*)(qg + (size_t)r * CI_ + u * 8);
        *(uint4*)(Qs + r * QST + u * 8) = v;
    }
    // ---- K: 32 x 64 ----
    const __half* kgb = kv + (size_t)b * 32 * KVW + h * 64;
#pragma unroll
    for (int it = 0; it < 2; it++) {
        int i = tid + it * 128;          // 0..255
        int l = i >> 3, u = i & 7;
        uint4 v = *(const uint4*)(kgb + (size_t)l * KVW + u * 8);
        *(uint4*)(Ks + l * QST + u * 8) = v;
    }
    // ---- V transposed: Vt[d][l] ----
    const __half* vgb = kgb + 768;
#pragma unroll
    for (int it = 0; it < 16; it++) {
        int i = tid + it * 128;          // 0..2047
        int l = i >> 6, d = i & 63;
        Vt[d * VST + l] = vgb[(size_t)l * KVW + d];
    }
    __syncthreads();

    const uint32_t qb = smem_u32(Qs);
    const uint32_t kb = smem_u32(Ks);
    const uint32_t vb = smem_u32(Vt);

    // hoisted K fragments: BkF[kc 0..3][ni2 0..1][4]
    uint32_t BkF[4][2][4];
#pragma unroll
    for (int kc = 0; kc < 4; kc++)
#pragma unroll
        for (int ni2 = 0; ni2 < 2; ni2++)
            ldsm_x4(BkF[kc][ni2],
                    kb + ((lane & 7) + ((lane >> 4) << 3) + ni2 * 16) * (QST * 2)
                       + kc * 32 + (((lane >> 3) & 1) << 4));
    // hoisted V fragments: BvF[kc 0..1][ni2 0..3][4]
    uint32_t BvF[2][4][4];
#pragma unroll
    for (int kc = 0; kc < 2; kc++)
#pragma unroll
        for (int ni2 = 0; ni2 < 4; ni2++)
            ldsm_x4(BvF[kc][ni2],
                    vb + ((lane & 7) + ((lane >> 4) << 3) + ni2 * 16) * (VST * 2)
                       + kc * 32 + (((lane >> 3) & 1) << 4));

    const int r = lane >> 2;        // row within 8-group
    const int cq = lane & 3;        // col-pair index

#pragma unroll
    for (int it = 0; it < 4; it++) {
        int t = w + it * 4;
        if (t >= 13) break;
        int r0 = t * 16;

        // A fragments of Q
        uint32_t Aq[4][4];
#pragma unroll
        for (int kc = 0; kc < 4; kc++)
            ldsm_x4(Aq[kc], qb + (r0 + (lane & 15)) * (QST * 2)
                              + kc * 32 + ((lane >> 4) << 4));

        // scores: 4 n8 frags over l=32
        float accs[4][4];
#pragma unroll
        for (int j = 0; j < 4; j++)
#pragma unroll
            for (int k = 0; k < 4; k++) accs[j][k] = 0.f;
#pragma unroll
        for (int kc = 0; kc < 4; kc++)
#pragma unroll
            for (int j = 0; j < 4; j++)
                mma_fp16(accs[j], Aq[kc], &BkF[kc][j >> 1][(j & 1) * 2]);

        // scale + row max (rows r and r+8)
        float m0 = -1e30f, m1 = -1e30f;
#pragma unroll
        for (int j = 0; j < 4; j++) {
            accs[j][0] *= 0.125f; accs[j][1] *= 0.125f;
            accs[j][2] *= 0.125f; accs[j][3] *= 0.125f;
            m0 = fmaxf(m0, fmaxf(accs[j][0], accs[j][1]));
            m1 = fmaxf(m1, fmaxf(accs[j][2], accs[j][3]));
        }
#pragma unroll
        for (int off = 1; off <= 2; off <<= 1) {
            m0 = fmaxf(m0, __shfl_xor_sync(0xffffffffu, m0, off));
            m1 = fmaxf(m1, __shfl_xor_sync(0xffffffffu, m1, off));
        }
        float s0 = 0.f, s1 = 0.f;
#pragma unroll
        for (int j = 0; j < 4; j++) {
            accs[j][0] = fexp(accs[j][0] - m0);
            accs[j][1] = fexp(accs[j][1] - m0);
            accs[j][2] = fexp(accs[j][2] - m1);
            accs[j][3] = fexp(accs[j][3] - m1);
            s0 += accs[j][0] + accs[j][1];
            s1 += accs[j][2] + accs[j][3];
        }
#pragma unroll
        for (int off = 1; off <= 2; off <<= 1) {
            s0 += __shfl_xor_sync(0xffffffffu, s0, off);
            s1 += __shfl_xor_sync(0xffffffffu, s1, off);
        }
        float inv0 = 1.0f / s0, inv1 = 1.0f / s1;

        // P as A-frags (C->A register identity)
        uint32_t Pa[2][4];
#pragma unroll
        for (int kc = 0; kc < 2; kc++) {
            int j0 = 2 * kc, j1 = 2 * kc + 1;
            Pa[kc][0] = pack_h2f(accs[j0][0] * inv0, accs[j0][1] * inv0);
            Pa[kc][1] = pack_h2f(accs[j0][2] * inv1, accs[j0][3] * inv1);
            Pa[kc][2] = pack_h2f(accs[j1][0] * inv0, accs[j1][1] * inv0);
            Pa[kc][3] = pack_h2f(accs[j1][2] * inv1, accs[j1][3] * inv1);
        }

        // PV: 8 n8 frags over d=64
        float acco[8][4];
#pragma unroll
        for (int j = 0; j < 8; j++)
#pragma unroll
            for (int k = 0; k < 4; k++) acco[j][k] = 0.f;
#pragma unroll
        for (int kc = 0; kc < 2; kc++)
#pragma unroll
            for (int j = 0; j < 8; j++)
                mma_fp16(acco[j], Pa[kc], &BvF[kc][j >> 1][(j & 1) * 2]);

        // store ctx + residual
        bool ok0 = (r0 + r) < 196;
        bool ok1 = (r0 + r + 8) < 196;
        size_t row0g = (size_t)(b * 196 + r0 + r) * CI_;
#pragma unroll
        for (int j = 0; j < 8; j++) {
            int col = h * 64 + j * 8 + cq * 2;
            if (ok0) {
                uint32_t rv = *(const uint32_t*)(vis_h + row0g + col);
                float2 rf = __half22float2(*(__half2*)&rv);
                *(uint32_t*)(f_h + row0g + col) =
                    pack_h2f(acco[j][0] + rf.x, acco[j][1] + rf.y);
            }
            if (ok1) {
                uint32_t rv = *(const uint32_t*)(vis_h + row0g + 8 * CI_ + col);
                float2 rf = __half22float2(*(__half2*)&rv);
                *(uint32_t*)(f_h + row0g + 8 * CI_ + col) =
                    pack_h2f(acco[j][2] + rf.x, acco[j][3] + rf.y);
            }
        }
    }
}

// -------------------- head reduce: sum 6 partials + bias; fill rel -------------
__global__ __launch_bounds__(256)
void reduce_head(const float* __restrict__ part, const float* __restrict__ b2,
                 float* __restrict__ out) {
    int i = blockIdx.x * blockDim.x + threadIdx.x;
    if (i >= NROWS) return;
    float a0 = b2[0], a1 = b2[1];
#pragma unroll
    for (int p = 0; p < 6; p++) {
        a0 += part[((size_t)p * NROWS + i) * 2];
        a1 += part[((size_t)p * NROWS + i) * 2 + 1];
    }
    out[(size_t)i * 2]     = a0;
    out[(size_t)i * 2 + 1] = a1;
    out[(size_t)NROWS * 2 + i] = 1.0f / 32.0f;   // rel_BN == 1/Lt exactly
}

// -------------------- host launch --------------------
extern "C" void kernel_launch(void* const* d_in, const int* in_sizes, int n_in,
                              void* d_out, int out_size) {
    const float* vis  = (const float*)d_in[0];
    const float* text = (const float*)d_in[1];
    const float* Wq   = (const float*)d_in[2];
    const float* bq   = (const float*)d_in[3];
    const float* Wk   = (const float*)d_in[4];
    const float* bk   = (const float*)d_in[5];
    const float* Wv   = (const float*)d_in[6];
    const float* bv   = (const float*)d_in[7];
    const float* W1   = (const float*)d_in[8];
    const float* b1   = (const float*)d_in[9];
    const float* W2   = (const float*)d_in[10];
    const float* b2   = (const float*)d_in[11];
    float* out = (float*)d_out;

    __half *vh, *th, *wq, *wkv, *w1, *fh, *qh, *kvh;
    float *bkv, *partp;
    cudaGetSymbolAddress((void**)&vh,   g_vis_h);
    cudaGetSymbolAddress((void**)&th,   g_text_h);
    cudaGetSymbolAddress((void**)&wq,   g_wqT);
    cudaGetSymbolAddress((void**)&wkv,  g_wkvT);
    cudaGetSymbolAddress((void**)&w1,   g_w1T);
    cudaGetSymbolAddress((void**)&fh,   g_fused_h);
    cudaGetSymbolAddress((void**)&qh,   g_qh);
    cudaGetSymbolAddress((void**)&kvh,  g_kvh);
    cudaGetSymbolAddress((void**)&bkv,  g_bkv);
    cudaGetSymbolAddress((void**)&partp, g_part);

    cudaFuncSetAttribute(gemm_mma<768, 768, 0, 1>, cudaFuncAttributeMaxDynamicSharedMemorySize, GEMM_SMEM);
    cudaFuncSetAttribute(gemm_mma<512, KVW, 0, 1>, cudaFuncAttributeMaxDynamicSharedMemorySize, GEMM_SMEM);
    cudaFuncSetAttribute(gemm_mma<768, 768, 1, 0>, cudaFuncAttributeMaxDynamicSharedMemorySize, GEMM_SMEM);

    // 1: convert vis -> fp16
    {
        int n4 = NROWS * CI_ / 4;
        cvt_kernel<<<(n4 + 255) / 256, 256>>>(vis, vh, n4);
    }
    // 2: convert text -> fp16
    {
        int n4 = KVROWS * CT_ / 4;
        cvt_kernel<<<(n4 + 255) / 256, 256>>>(text, th, n4);
    }
    // 3: transpose Wq
    transpose_cvt<<<dim3(CI_ / 32, CI_ / 32), 256>>>(Wq, wq, CI_, CI_);
    // 4: Q projection (fp16 out)  <-- profiler slot
    gemm_mma<768, 768, 0, 1><<<dim3(6, NROWS / 128), 256, GEMM_SMEM>>>(
        vh, wq, bq, qh, nullptr, nullptr);
    // 5-6: transpose Wk, Wv into fused wkv
    transpose_cvt<<<dim3(CI_ / 32, CT_ / 32), 256>>>(Wk, wkv, CT_, CI_);
    transpose_cvt<<<dim3(CI_ / 32, CT_ / 32), 256>>>(Wv, wkv + (size_t)768 * CT_, CT_, CI_);
    // 7: bias concat
    concat_bias<<<6, 256>>>(bk, bv, bkv);
    // 8: fused K|V projection (fp16 out)
    gemm_mma<512, KVW, 0, 1><<<dim3(12, KVROWS / 128), 256, GEMM_SMEM>>>(
        th, wkv, bkv, kvh, nullptr, nullptr);
    // 9: MMA attention + residual (fp16 vis) -> fused fp16
    attn_mma<<<dim3(12, B_), 128>>>(qh, kvh, vh, fh);
    // 10: transpose W1
    transpose_cvt<<<dim3(CI_ / 32, CI_ / 32), 256>>>(W1, w1, CI_, CI_);
    // 11: MLP1 + gelu + fused W2 head -> partials
    gemm_mma<768, 768, 1, 0><<<dim3(6, NROWS / 128), 256, GEMM_SMEM>>>(
        fh, w1, b1, nullptr, W2, partp);
    // 12: reduce partials + bias; fill rel
    reduce_head<<<(NROWS + 255) / 256, 256>>>(partp, b2, out);
}